// round 16
// baseline (speedup 1.0000x reference)
#include <cuda_runtime.h>
#include <cuda_fp16.h>
#include <cstdint>

// Problem constants
#define B_   2
#define S_   2048
#define D_   1024
#define H_   16
#define DH_  64
#define N_   (B_ * S_)   // 4096 tokens
#define K_   1024

// ---------------------------------------------------------------------------
// Scratch (device globals — no allocation allowed)
// ---------------------------------------------------------------------------
__device__ float  g_v  [B_ * H_ * S_ * DH_];   // V head-major fp32 (pre-transpose)
__device__ __half g_qh [B_ * H_ * S_ * DH_];   // Q head-major fp16, pre-scaled by 0.125
__device__ __half g_kh [B_ * H_ * S_ * DH_];   // K head-major fp16
__device__ __half g_vth[B_ * H_ * DH_ * S_];   // V^T [b][h][dh][s] fp16
__device__ float  g_att[N_ * D_];              // attention output [n][h*64+dh]

// ---------------------------------------------------------------------------
// Helpers
// ---------------------------------------------------------------------------
__device__ __forceinline__ uint32_t f2h2(float x, float y) {
    __half2 h = __floats2half2_rn(x, y);
    return *(uint32_t*)&h;
}
__device__ __forceinline__ void mma_f16(float* c, const uint32_t* a, const uint32_t* b) {
    asm volatile(
        "mma.sync.aligned.m16n8k16.row.col.f32.f16.f16.f32 "
        "{%0,%1,%2,%3}, {%4,%5,%6,%7}, {%8,%9}, {%0,%1,%2,%3};"
        : "+f"(c[0]), "+f"(c[1]), "+f"(c[2]), "+f"(c[3])
        : "r"(a[0]), "r"(a[1]), "r"(a[2]), "r"(a[3]), "r"(b[0]), "r"(b[1]));
}
__device__ __forceinline__ void cpa16(uint32_t dst, const void* src) {
    asm volatile("cp.async.cg.shared.global [%0], [%1], 16;" :: "r"(dst), "l"(src));
}
#define CPA_COMMIT() asm volatile("cp.async.commit_group;" ::: "memory")
#define CPA_WAIT1()  asm volatile("cp.async.wait_group 1;" ::: "memory")
#define CPA_WAIT0()  asm volatile("cp.async.wait_group 0;" ::: "memory")

// ---------------------------------------------------------------------------
// fp16 mma.sync TN GEMM, double-buffered smem (one sync per k-chunk).
// C[n,o] = sum_k A[n,k]*W[o,k] + bias[o].
// mode==1 (QKV): z=0 -> fp16 Q scaled 0.125; z=1 -> fp16 K; z=2 -> fp32 V.
// mode==0: fp32 row-major to C0.
// ---------------------------------------------------------------------------
#define KPH 40

__global__ void __launch_bounds__(256)
gemmh(const float* __restrict__ A,
      const float* __restrict__ W0, const float* __restrict__ W1,
      const float* __restrict__ W2,
      const float* __restrict__ b0, const float* __restrict__ b1,
      const float* __restrict__ b2,
      void* C0, void* C1, void* C2,
      int mode)
{
    __shared__ uint16_t Ah[2][128 * KPH];
    __shared__ uint16_t Bh[2][128 * KPH];

    const int z = blockIdx.z;
    const float* W    = (z == 0) ? W0 : (z == 1) ? W1 : W2;
    const float* bias = (z == 0) ? b0 : (z == 1) ? b1 : b2;

    const int t    = threadIdx.x;
    const int wid  = t >> 5;
    const int lane = t & 31;
    const int bn = blockIdx.x;
    const int bm = blockIdx.y;

    const int wr = (wid & 1) << 6;
    const int wc = (wid >> 1) << 5;
    const int g   = lane >> 2;
    const int tig = lane & 3;

    const int lrow = t >> 1;
    const int lkc  = (t & 1) * 16;

    const float* Ag = A + (size_t)(bm * 128 + lrow) * K_ + lkc;
    const float* Wg = W + (size_t)(bn * 128 + lrow) * K_ + lkc;

    float acc[4][4][4];
#pragma unroll
    for (int mt = 0; mt < 4; mt++)
#pragma unroll
        for (int nt = 0; nt < 4; nt++)
#pragma unroll
            for (int r = 0; r < 4; r++) acc[mt][nt][r] = 0.f;

    float4 pa[4], pb[4];
#pragma unroll
    for (int i = 0; i < 4; i++) {
        pa[i] = *(const float4*)(Ag + 4 * i);
        pb[i] = *(const float4*)(Wg + 4 * i);
    }

    for (int c = 0; c < 32; c++) {
        const int buf = c & 1;
#pragma unroll
        for (int i = 0; i < 4; i++) {
            *(uint2*)&Ah[buf][lrow * KPH + lkc + 4 * i] =
                make_uint2(f2h2(pa[i].x, pa[i].y), f2h2(pa[i].z, pa[i].w));
            *(uint2*)&Bh[buf][lrow * KPH + lkc + 4 * i] =
                make_uint2(f2h2(pb[i].x, pb[i].y), f2h2(pb[i].z, pb[i].w));
        }
        __syncthreads();
        if (c < 31) {
            const float* An = Ag + (size_t)(c + 1) * 32;
            const float* Wn = Wg + (size_t)(c + 1) * 32;
#pragma unroll
            for (int i = 0; i < 4; i++) {
                pa[i] = *(const float4*)(An + 4 * i);
                pb[i] = *(const float4*)(Wn + 4 * i);
            }
        }
#pragma unroll
        for (int ks = 0; ks < 2; ks++) {
            const int k0 = 16 * ks + 2 * tig;
            uint32_t af[4][4], bf[4][2];
#pragma unroll
            for (int mt = 0; mt < 4; mt++) {
                const int r = wr + 16 * mt + g;
                af[mt][0] = *(const uint32_t*)&Ah[buf][r * KPH + k0];
                af[mt][1] = *(const uint32_t*)&Ah[buf][(r + 8) * KPH + k0];
                af[mt][2] = *(const uint32_t*)&Ah[buf][r * KPH + k0 + 8];
                af[mt][3] = *(const uint32_t*)&Ah[buf][(r + 8) * KPH + k0 + 8];
            }
#pragma unroll
            for (int nt = 0; nt < 4; nt++) {
                const int o = wc + 8 * nt + g;
                bf[nt][0] = *(const uint32_t*)&Bh[buf][o * KPH + k0];
                bf[nt][1] = *(const uint32_t*)&Bh[buf][o * KPH + k0 + 8];
            }
#pragma unroll
            for (int mt = 0; mt < 4; mt++)
#pragma unroll
                for (int nt = 0; nt < 4; nt++)
                    mma_f16(acc[mt][nt], af[mt], bf[nt]);
        }
    }

    const int rbase = bm * 128 + wr + g;
    const int cbase = bn * 128 + wc + 2 * tig;
#pragma unroll
    for (int mt = 0; mt < 4; mt++) {
#pragma unroll
        for (int nt = 0; nt < 4; nt++) {
            const int col = cbase + nt * 8;
            const float bx = bias[col], by = bias[col + 1];
#pragma unroll
            for (int h2 = 0; h2 < 2; h2++) {
                const int n = rbase + mt * 16 + 8 * h2;
                const float vx = acc[mt][nt][2 * h2 + 0] + bx;
                const float vy = acc[mt][nt][2 * h2 + 1] + by;
                if (mode == 1) {
                    const int b  = n >> 11;
                    const int s  = n & (S_ - 1);
                    const int hh = col >> 6;
                    const int dh = col & 63;
                    const size_t off =
                        (((size_t)(b * H_ + hh)) * S_ + s) * DH_ + dh;
                    if (z == 0) {
                        *(__half2*)((__half*)C0 + off) =
                            __floats2half2_rn(vx * 0.125f, vy * 0.125f);
                    } else if (z == 1) {
                        *(__half2*)((__half*)C1 + off) =
                            __floats2half2_rn(vx, vy);
                    } else {
                        *(float2*)((float*)C2 + off) = make_float2(vx, vy);
                    }
                } else {
                    *(float2*)((float*)C0 + (size_t)n * D_ + col) =
                        make_float2(vx, vy);
                }
            }
        }
    }
}

// ---------------------------------------------------------------------------
// V transpose: fp32 [b][h][s][dh] -> fp16 [b][h][dh][s]
// ---------------------------------------------------------------------------
__global__ void __launch_bounds__(256)
vtrans(const float* __restrict__ v, __half* __restrict__ vt)
{
    __shared__ float tile[64][68];
    const int sb = blockIdx.x;
    const int h  = blockIdx.y;
    const int b  = blockIdx.z;
    const int t  = threadIdx.x;
    const int r  = t >> 2;
    const int c0 = (t & 3) * 16;

    const float* src = v + (((size_t)(b * H_ + h)) * S_ + sb * 64) * DH_;
#pragma unroll
    for (int i = 0; i < 4; i++) {
        float4 f = *(const float4*)(src + (size_t)r * DH_ + c0 + 4 * i);
        tile[r][c0 + 4 * i + 0] = f.x;
        tile[r][c0 + 4 * i + 1] = f.y;
        tile[r][c0 + 4 * i + 2] = f.z;
        tile[r][c0 + 4 * i + 3] = f.w;
    }
    __syncthreads();

    // write dh-row r, s chunk c0..c0+15
    uint32_t w[8];
#pragma unroll
    for (int j = 0; j < 8; j++)
        w[j] = f2h2(tile[c0 + 2 * j][r], tile[c0 + 2 * j + 1][r]);
    __half* dst = vt + (((size_t)(b * H_ + h)) * DH_ + r) * S_ + sb * 64 + c0;
    *(uint4*)(dst)     = make_uint4(w[0], w[1], w[2], w[3]);
    *(uint4*)(dst + 8) = make_uint4(w[4], w[5], w[6], w[7]);
}

// ---------------------------------------------------------------------------
// HMMA flash attention with fp16 sources + cp.async double buffering.
// 64 q-rows/CTA, 4 warps, 64-key blocks, P register-resident.
// Dynamic smem (bytes):
//   Qh   [64*72 halves]        @ 0      (9216)
//   Kh[2][64*72 halves]        @ 9216   (18432)
//   Vt[2][64*72 halves]        @ 27648  (18432)
//   msk  [2048 ints]           @ 46080  (8192)
// ---------------------------------------------------------------------------
#define FSTR 72
#define QH_OFF  0
#define KH_OFF  9216
#define VT_OFF  27648
#define MSK_OFF 46080
#define FL_SMEM 54272

__global__ void __launch_bounds__(128)
flash_h(const int* __restrict__ mask, float* __restrict__ out)
{
    extern __shared__ char fsm[];
    uint16_t* Qh  = (uint16_t*)(fsm + QH_OFF);
    int*      msk = (int*)     (fsm + MSK_OFF);
    const uint32_t sbase = (uint32_t)__cvta_generic_to_shared(fsm);

    const int qb = blockIdx.x;
    const int h  = blockIdx.y;
    const int b  = blockIdx.z;

    const __half* Qg = g_qh  + (((size_t)(b * H_ + h)) * S_ + qb * 64) * DH_;
    const __half* Kg = g_kh  + ((size_t)(b * H_ + h)) * S_ * DH_;
    const __half* Vg = g_vth + ((size_t)(b * H_ + h)) * DH_ * S_;

    const int t    = threadIdx.x;
    const int wid  = t >> 5;
    const int lane = t & 31;
    const int g    = lane >> 2;
    const int tig  = lane & 3;

    // ---- preload Q tile (fp16, 512 x 16B chunks) and full mask row ----
#pragma unroll
    for (int i = 0; i < 4; i++) {
        const int c = t * 4 + i;            // 0..511
        const int row = c >> 3, col = c & 7;
        *(uint4*)((char*)Qh + row * (FSTR * 2) + col * 16) =
            *(const uint4*)((const char*)Qg + row * (DH_ * 2) + col * 16);
        ((uint4*)msk)[c] = ((const uint4*)(mask + (size_t)b * S_))[c];
    }
    __syncthreads();

    // Q fragments: rows 16*wid+g / +8, dh 16kt..+15
    uint32_t qf[4][4];
#pragma unroll
    for (int kt = 0; kt < 4; kt++) {
        const int base = (16 * wid + g) * FSTR + 16 * kt + 2 * tig;
        qf[kt][0] = *(const uint32_t*)&Qh[base];
        qf[kt][1] = *(const uint32_t*)&Qh[base + 8 * FSTR];
        qf[kt][2] = *(const uint32_t*)&Qh[base + 8];
        qf[kt][3] = *(const uint32_t*)&Qh[base + 8 * FSTR + 8];
    }

    // async tile loader: 512 chunks of 16B, smem row stride 144B
    auto loadKV = [&](int kb, int p) {
        const uint32_t kb_s = sbase + KH_OFF + p * 9216;
        const uint32_t vb_s = sbase + VT_OFF + p * 9216;
        const __half* ks = Kg + (size_t)(kb * 64) * DH_;
        const __half* vs = Vg + kb * 64;
#pragma unroll
        for (int i = 0; i < 4; i++) {
            const int c = t * 4 + i;
            const int row = c >> 3, col = c & 7;
            cpa16(kb_s + row * 144 + col * 16,
                  (const char*)ks + row * (DH_ * 2) + col * 16);
            cpa16(vb_s + row * 144 + col * 16,
                  (const char*)vs + (size_t)row * (S_ * 2) + col * 16);
        }
    };

    float o[8][4];
#pragma unroll
    for (int nt = 0; nt < 8; nt++)
#pragma unroll
        for (int r = 0; r < 4; r++) o[nt][r] = 0.f;
    float mA = -1e30f, mB = -1e30f, lA = 0.f, lB = 0.f;

    loadKV(0, 0);
    CPA_COMMIT();

    for (int kb = 0; kb < S_ / 64; kb++) {
        const int p = kb & 1;
        if (kb + 1 < S_ / 64) {
            loadKV(kb + 1, p ^ 1);
            CPA_COMMIT();
            CPA_WAIT1();
        } else {
            CPA_WAIT0();
        }
        __syncthreads();

        const uint16_t* Kh = (const uint16_t*)(fsm + KH_OFF + p * 9216);
        const uint16_t* Vt = (const uint16_t*)(fsm + VT_OFF + p * 9216);
        const int* mrow = msk + kb * 64;

        // ---- QK^T (Q pre-scaled by 0.125) ----
        float sc[8][4];
#pragma unroll
        for (int nt = 0; nt < 8; nt++)
#pragma unroll
            for (int r = 0; r < 4; r++) sc[nt][r] = 0.f;
#pragma unroll
        for (int kt = 0; kt < 4; kt++) {
#pragma unroll
            for (int nt = 0; nt < 8; nt++) {
                uint32_t bf[2];
                const int base = (8 * nt + g) * FSTR + 16 * kt + 2 * tig;
                bf[0] = *(const uint32_t*)&Kh[base];
                bf[1] = *(const uint32_t*)&Kh[base + 8];
                mma_f16(sc[nt], qf[kt], bf);
            }
        }

        // ---- mask + online softmax (rows g and g+8) ----
        float mxA = -1e30f, mxB = -1e30f;
#pragma unroll
        for (int nt = 0; nt < 8; nt++) {
            const bool ok0 = mrow[8 * nt + 2 * tig] != 0;
            const bool ok1 = mrow[8 * nt + 2 * tig + 1] != 0;
            if (!ok0) { sc[nt][0] = -1e9f; sc[nt][2] = -1e9f; }
            if (!ok1) { sc[nt][1] = -1e9f; sc[nt][3] = -1e9f; }
            mxA = fmaxf(mxA, fmaxf(sc[nt][0], sc[nt][1]));
            mxB = fmaxf(mxB, fmaxf(sc[nt][2], sc[nt][3]));
        }
        mxA = fmaxf(mxA, __shfl_xor_sync(0xffffffffu, mxA, 1));
        mxA = fmaxf(mxA, __shfl_xor_sync(0xffffffffu, mxA, 2));
        mxB = fmaxf(mxB, __shfl_xor_sync(0xffffffffu, mxB, 1));
        mxB = fmaxf(mxB, __shfl_xor_sync(0xffffffffu, mxB, 2));

        const float mnA = fmaxf(mA, mxA);
        const float mnB = fmaxf(mB, mxB);
        const float aA = __expf(mA - mnA);
        const float aB = __expf(mB - mnB);
        float sumA = 0.f, sumB = 0.f;
#pragma unroll
        for (int nt = 0; nt < 8; nt++) {
            sc[nt][0] = __expf(sc[nt][0] - mnA);
            sc[nt][1] = __expf(sc[nt][1] - mnA);
            sc[nt][2] = __expf(sc[nt][2] - mnB);
            sc[nt][3] = __expf(sc[nt][3] - mnB);
            sumA += sc[nt][0] + sc[nt][1];
            sumB += sc[nt][2] + sc[nt][3];
        }
        sumA += __shfl_xor_sync(0xffffffffu, sumA, 1);
        sumA += __shfl_xor_sync(0xffffffffu, sumA, 2);
        sumB += __shfl_xor_sync(0xffffffffu, sumB, 1);
        sumB += __shfl_xor_sync(0xffffffffu, sumB, 2);
        lA = lA * aA + sumA; mA = mnA;
        lB = lB * aB + sumB; mB = mnB;
#pragma unroll
        for (int nt = 0; nt < 8; nt++) {
            o[nt][0] *= aA; o[nt][1] *= aA;
            o[nt][2] *= aB; o[nt][3] *= aB;
        }

        // ---- pack P fragments (register-only) ----
        uint32_t pa[4][4];
#pragma unroll
        for (int kt = 0; kt < 4; kt++) {
            pa[kt][0] = f2h2(sc[2 * kt][0],     sc[2 * kt][1]);
            pa[kt][1] = f2h2(sc[2 * kt][2],     sc[2 * kt][3]);
            pa[kt][2] = f2h2(sc[2 * kt + 1][0], sc[2 * kt + 1][1]);
            pa[kt][3] = f2h2(sc[2 * kt + 1][2], sc[2 * kt + 1][3]);
        }

        // ---- O += P @ V ----
#pragma unroll
        for (int kt = 0; kt < 4; kt++) {
#pragma unroll
            for (int nt = 0; nt < 8; nt++) {
                uint32_t bf[2];
                const int base = (8 * nt + g) * FSTR + 16 * kt + 2 * tig;
                bf[0] = *(const uint32_t*)&Vt[base];
                bf[1] = *(const uint32_t*)&Vt[base + 8];
                mma_f16(o[nt], pa[kt], bf);
            }
        }
        __syncthreads();   // all reads of buf p done before iter kb+1 overwrites it
    }

    // Epilogue
    const float invA = 1.f / lA;
    const float invB = 1.f / lB;
    const int rowA = qb * 64 + 16 * wid + g;
    const int rowB = rowA + 8;
#pragma unroll
    for (int nt = 0; nt < 8; nt++) {
        const int col = 8 * nt + 2 * tig;
        float2 va = make_float2(o[nt][0] * invA, o[nt][1] * invA);
        float2 vb = make_float2(o[nt][2] * invB, o[nt][3] * invB);
        *(float2*)(out + ((size_t)(b * S_ + rowA)) * D_ + h * DH_ + col) = va;
        *(float2*)(out + ((size_t)(b * S_ + rowB)) * D_ + h * DH_ + col) = vb;
    }
}

// ---------------------------------------------------------------------------
// Launch
// ---------------------------------------------------------------------------
extern "C" void kernel_launch(void* const* d_in, const int* in_sizes, int n_in,
                              void* d_out, int out_size)
{
    (void)in_sizes; (void)n_in; (void)out_size;
    const float* x    = (const float*)d_in[0];
    const int*   mask = (const int*)  d_in[1];
    const float* Wq   = (const float*)d_in[2];
    const float* bq   = (const float*)d_in[3];
    const float* Wk   = (const float*)d_in[4];
    const float* bk   = (const float*)d_in[5];
    const float* Wv   = (const float*)d_in[6];
    const float* bv   = (const float*)d_in[7];
    const float* Wo   = (const float*)d_in[8];
    const float* bo   = (const float*)d_in[9];
    float* out = (float*)d_out;

    void *qh, *kh, *vp, *vth, *ap;
    cudaGetSymbolAddress(&qh,  g_qh);
    cudaGetSymbolAddress(&kh,  g_kh);
    cudaGetSymbolAddress(&vp,  g_v);
    cudaGetSymbolAddress(&vth, g_vth);
    cudaGetSymbolAddress(&ap,  g_att);

    static int attr_done = 0;
    if (!attr_done) {
        cudaFuncSetAttribute(flash_h,
                             cudaFuncAttributeMaxDynamicSharedMemorySize, FL_SMEM);
        attr_done = 1;
    }

    // Fused Q/K/V projections (Q,K -> fp16; V -> fp32)
    gemmh<<<dim3(D_ / 128, N_ / 128, 3), 256>>>(
        x, Wq, Wk, Wv, bq, bk, bv, qh, kh, vp, 1);

    // V transpose to fp16 [b][h][dh][s]
    vtrans<<<dim3(S_ / 64, H_, B_), 256>>>((const float*)vp, (__half*)vth);

    // Flash attention (fp16 HMMA, cp.async double-buffered)
    flash_h<<<dim3(S_ / 64, H_, B_), 128, FL_SMEM>>>(mask, (float*)ap);

    // Output projection (fp32 out)
    gemmh<<<dim3(D_ / 128, N_ / 128, 1), 256>>>(
        (const float*)ap, Wo, Wo, Wo, bo, bo, bo, out, out, out, 0);
}